// round 16
// baseline (speedup 1.0000x reference)
#include <cuda_runtime.h>

#define NPT 4096
#define INV_EPS 10.0f
#define ITERS 50
#define FB 296                     // 2 blocks/SM on 148 SMs, all resident -> no deadlock
#define NQUADS (NPT / 4)           // 1024 row-quads
#define NRED 256                   // reducer blocks (16 cols each)

// Scratch (static device arrays: allocation-free per harness rules)
__device__ float g_K32[(size_t)NPT * NPT];   // K = exp(-C/eps), fp32 row-major (64 MB, L2-resident)
// colpart layout: [jc (64 col-groups)][blk (296)][c (64)] -> contiguous reduce streams
__device__ __align__(16) float g_colpart[64 * FB * 64];
__device__ __align__(16) float g_a[NPT];
__device__ __align__(16) float g_b[NPT];
__device__ float g_part[FB];
__device__ int   g_c1;                       // arrive: colpart ready (target FB*it)
__device__ int   g_c2;                       // arrive: b ready       (target NRED*it)
__device__ int   g_c3;                       // arrive: epilogue partial ready

// ---------------------------------------------------------------------------
// ONE persistent kernel: init (fused into iter 0), 50 Sinkhorn iterations,
// epilogue (pi, C, cost) and final reduction. Single graph node.
// Per iteration (K read at most once; iter 0 reads K zero times):
//   dot   : a_i = mu/(K b)_i            (warp-sliced, K rows in registers)
//   scale : colpart[jc][blk][c] += a_i K_ij     (register reuse)
//   sync1 -> 256 reducer blocks: b_j = nu/colsum (contiguous streams) -> sync2
// Counters monotone within launch; reset by last epilogue block (replay-safe).
// ---------------------------------------------------------------------------
__global__ void __launch_bounds__(256, 2) k_all(
    const float* __restrict__ x, const float* __restrict__ y,
    float* __restrict__ out, float* __restrict__ pi, float* __restrict__ Cout,
    int do_write, float mu, float nu)
{
    __shared__ float sy0[NPT], sy1[NPT];          // 32 KB staged y
    __shared__ float part[2][8][4];
    __shared__ float sp[16][17];
    __shared__ float sred[256];
    __shared__ int   s_last;

    const int t    = threadIdx.x;
    const int w    = t >> 5;
    const int lane = t & 31;
    const int jq0  = w << 7;                      // float4 base of warp's 512-col slice
    const int q0 = (int)(((long long)blockIdx.x * NQUADS) / FB);
    const int q1 = (int)(((long long)(blockIdx.x + 1) * NQUADS) / FB);
    const int jc_base = (w << 3) + (lane >> 4);
    const int c_col   = (lane & 15) << 2;

    // stage y (read once per block)
    for (int u = t; u < NPT; u += 256) {
        const float2 v = ((const float2*)y)[u];
        sy0[u] = v.x; sy1[u] = v.y;
    }
    __syncthreads();

    for (int it = 0; it < ITERS; it++) {
        float4 bseg[4];
        if (it) {
#pragma unroll
            for (int q = 0; q < 4; q++)
                bseg[q] = __ldcg((const float4*)g_b + jq0 + (q << 5) + lane);
        }

        float4 acc[4] = {{0.f,0.f,0.f,0.f},{0.f,0.f,0.f,0.f},
                         {0.f,0.f,0.f,0.f},{0.f,0.f,0.f,0.f}};

        for (int qd = q0; qd < q1; qd++) {
            const int rb  = qd << 2;
            const int buf = qd & 1;
            float4 kr[4][4];
            float  p[4];

            if (it == 0) {
                // iter 0: produce K in registers (b == 1 -> dot is a plain sum),
                // then store K. No K read this iteration.
                float xr0[4], xr1[4];
#pragma unroll
                for (int r = 0; r < 4; r++) {
                    xr0[r] = x[2 * (rb + r)];
                    xr1[r] = x[2 * (rb + r) + 1];
                }
#pragma unroll
                for (int r = 0; r < 4; r++) p[r] = 0.f;
#pragma unroll
                for (int q = 0; q < 4; q++) {
                    const int ci = jq0 + (q << 5) + lane;
                    const float4 y0v = *(const float4*)&sy0[ci << 2];
                    const float4 y1v = *(const float4*)&sy1[ci << 2];
#pragma unroll
                    for (int r = 0; r < 4; r++) {
                        float4 k;
                        k.x = __expf(-INV_EPS * (fabsf(xr0[r] - y0v.x) + fabsf(xr1[r] - y1v.x)));
                        k.y = __expf(-INV_EPS * (fabsf(xr0[r] - y0v.y) + fabsf(xr1[r] - y1v.y)));
                        k.z = __expf(-INV_EPS * (fabsf(xr0[r] - y0v.z) + fabsf(xr1[r] - y1v.z)));
                        k.w = __expf(-INV_EPS * (fabsf(xr0[r] - y0v.w) + fabsf(xr1[r] - y1v.w)));
                        kr[r][q] = k;
                        p[r] += k.x + k.y + k.z + k.w;
                        ((float4*)(g_K32 + (size_t)(rb + r) * NPT))[ci] = k;
                    }
                }
            } else {
#pragma unroll
                for (int r = 0; r < 4; r++) {
                    const float4* __restrict__ Kp =
                        (const float4*)(g_K32 + (size_t)(rb + r) * NPT) + jq0;
                    float s = 0.f;
#pragma unroll
                    for (int q = 0; q < 4; q++) {
                        const float4 k = Kp[(q << 5) + lane];
                        kr[r][q] = k;
                        s += k.x * bseg[q].x + k.y * bseg[q].y
                           + k.z * bseg[q].z + k.w * bseg[q].w;
                    }
                    p[r] = s;
                }
            }

#pragma unroll
            for (int o = 16; o; o >>= 1) {
                p[0] += __shfl_xor_sync(0xFFFFFFFFu, p[0], o);
                p[1] += __shfl_xor_sync(0xFFFFFFFFu, p[1], o);
                p[2] += __shfl_xor_sync(0xFFFFFFFFu, p[2], o);
                p[3] += __shfl_xor_sync(0xFFFFFFFFu, p[3], o);
            }
            if (lane == 0) {
                part[buf][w][0] = p[0]; part[buf][w][1] = p[1];
                part[buf][w][2] = p[2]; part[buf][w][3] = p[3];
            }
            __syncthreads();                      // single barrier per quad

            float a[4];
#pragma unroll
            for (int r = 0; r < 4; r++) {
                float s = 0.f;
#pragma unroll
                for (int ww = 0; ww < 8; ww++) s += part[buf][ww][r];  // fixed order
                a[r] = mu / s;
            }
            if (it == ITERS - 1 && t < 4) g_a[rb + t] = a[t];

#pragma unroll
            for (int r = 0; r < 4; r++) {
#pragma unroll
                for (int q = 0; q < 4; q++) {
                    acc[q].x = fmaf(a[r], kr[r][q].x, acc[q].x);
                    acc[q].y = fmaf(a[r], kr[r][q].y, acc[q].y);
                    acc[q].z = fmaf(a[r], kr[r][q].z, acc[q].z);
                    acc[q].w = fmaf(a[r], kr[r][q].w, acc[q].w);
                }
            }
        }

        // colpart write (256B contiguous per half-warp), then grid arrive
#pragma unroll
        for (int q = 0; q < 4; q++) {
            const int jc = jc_base + (q << 1);
            *(float4*)(g_colpart + (((size_t)jc * FB + blockIdx.x) << 6) + c_col) = acc[q];
        }
        __threadfence();
        __syncthreads();
        if (t == 0) atomicAdd(&g_c1, 1);

        // reduce phase: 256 blocks, 16 cols each
        if (blockIdx.x < NRED) {
            if (t == 0) {
                volatile int* v = &g_c1;
                const int tgt = FB * (it + 1);
                while (*v < tgt) __nanosleep(32);
            }
            __syncthreads();
            __threadfence();

            const int jc  = blockIdx.x >> 2;
            const int qr  = blockIdx.x & 3;
            const int col = t & 15;
            const int ph  = t >> 4;               // 16 phases, 18-19 blocks each
            const int b0  = (ph * FB) >> 4;
            const int b1  = ((ph + 1) * FB) >> 4;
            float s = 0.f;
            for (int bb = b0; bb < b1; bb++)
                s += __ldcg(&g_colpart[(((size_t)jc * FB + bb) << 6) + (qr << 4) + col]);
            sp[ph][col] = s;
            __syncthreads();
            if (t < 16) {
                float ss = 0.f;
#pragma unroll
                for (int p2 = 0; p2 < 16; p2++) ss += sp[p2][t];   // fixed order
                g_b[(jc << 6) + (qr << 4) + t] = nu / ss;
            }
            __threadfence();
            __syncthreads();
            if (t == 0) atomicAdd(&g_c2, 1);
        }

        // all blocks wait until b is ready
        if (t == 0) {
            volatile int* v = &g_c2;
            const int tgt = NRED * (it + 1);
            while (*v < tgt) __nanosleep(32);
        }
        __syncthreads();
        __threadfence();
    }

    // ---- fused epilogue: pi = a K b, C from x/y, deterministic cost ----
    float4 bseg[4];
#pragma unroll
    for (int q = 0; q < 4; q++)
        bseg[q] = __ldcg((const float4*)g_b + jq0 + (q << 5) + lane);

    float csum = 0.f;
    for (int qd = q0; qd < q1; qd++) {
        const int rb = qd << 2;
#pragma unroll
        for (int r = 0; r < 4; r++) {
            const int row = rb + r;
            const float a   = g_a[row];
            const float xi0 = x[2 * row];
            const float xi1 = x[2 * row + 1];
            const float4* __restrict__ Kp =
                (const float4*)(g_K32 + (size_t)row * NPT) + jq0;
#pragma unroll
            for (int q = 0; q < 4; q++) {
                const int ci = jq0 + (q << 5) + lane;
                const float4 k   = Kp[(q << 5) + lane];
                const float4 y0v = *(const float4*)&sy0[ci << 2];
                const float4 y1v = *(const float4*)&sy1[ci << 2];
                float c4[4], p4[4];
                c4[0] = fabsf(xi0 - y0v.x) + fabsf(xi1 - y1v.x);
                c4[1] = fabsf(xi0 - y0v.y) + fabsf(xi1 - y1v.y);
                c4[2] = fabsf(xi0 - y0v.z) + fabsf(xi1 - y1v.z);
                c4[3] = fabsf(xi0 - y0v.w) + fabsf(xi1 - y1v.w);
                p4[0] = (a * k.x) * bseg[q].x;
                p4[1] = (a * k.y) * bseg[q].y;
                p4[2] = (a * k.z) * bseg[q].z;
                p4[3] = (a * k.w) * bseg[q].w;
                csum += p4[0]*c4[0] + p4[1]*c4[1] + p4[2]*c4[2] + p4[3]*c4[3];
                if (do_write) {
                    const size_t o = (size_t)row * NPT + ((size_t)ci << 2);
                    pi[o+0] = p4[0]; pi[o+1] = p4[1]; pi[o+2] = p4[2]; pi[o+3] = p4[3];
                    Cout[o+0] = c4[0]; Cout[o+1] = c4[1]; Cout[o+2] = c4[2]; Cout[o+3] = c4[3];
                }
            }
        }
    }

    // deterministic block reduction of cost partial
    sred[t] = csum;
    __syncthreads();
#pragma unroll
    for (int o = 128; o; o >>= 1) {
        if (t < o) sred[t] += sred[t + o];
        __syncthreads();
    }
    if (t == 0) {
        g_part[blockIdx.x] = sred[0];
        __threadfence();
        s_last = (atomicAdd(&g_c3, 1) == FB - 1);
    }
    __syncthreads();

    // last-arriving block: fixed-order final sum + counter reset (replay-safe)
    if (s_last) {
        __threadfence();
        float v = 0.f;
        for (int u = t; u < FB; u += 256) v += __ldcg(&g_part[u]);
        sred[t] = v;
        __syncthreads();
#pragma unroll
        for (int o = 128; o; o >>= 1) {
            if (t < o) sred[t] += sred[t + o];
            __syncthreads();
        }
        if (t == 0) {
            out[0] = sred[0];                      // cost^(1/P), P=1
            g_c1 = 0; g_c2 = 0; g_c3 = 0;
        }
    }
}

extern "C" void kernel_launch(void* const* d_in, const int* in_sizes, int n_in,
                              void* d_out, int out_size) {
    const float* x = (const float*)d_in[0];
    const float* y = (const float*)d_in[1];
    float* out = (float*)d_out;

    const float mu = 1.0f / (float)NPT + 1e-8f;  // exp(log_mu) == exp(log_nu)
    const float nu = mu;

    // Output layout (reference return order): [cost, pi (N*N), C (N*N)]
    const size_t nn = (size_t)NPT * NPT;
    const int do_write = (out_size >= (int)(1 + 2 * nn)) ? 1 : 0;
    float* pi = out + 1;
    float* C  = out + 1 + nn;

    k_all<<<FB, 256>>>(x, y, out, pi, C, do_write, mu, nu);
}